// round 5
// baseline (speedup 1.0000x reference)
#include <cuda_runtime.h>

// ---------------------------------------------------------------------------
// NeuralODEModel: persistent per-thread dopri5 (R3 shape: 224thr x 147 CTAs,
// 7 warps/SM) with layer-1 weights moved to __constant__ memory so the
// warp-uniform weight loads ride the constant/uniform port (LDCU) instead of
// the saturated L1/LSU path. W2 + per-thread cg stay in SMEM.
// Prep kernel packs weights into a __device__ staging buffer; a D2D
// cudaMemcpyToSymbolAsync copies it into constant memory (graph-capturable).
// ---------------------------------------------------------------------------

#define B_TOTAL 32768
#define T_STEPS 64
#define N_INJ   8
#define SID     7
#define SHD     16
#define OHD     16
#define MID     64
#define BLOCK   224
#define GRID    147   // 147*224 = 32928 >= 32768

typedef unsigned long long u64;

// ---- constant-memory weight pack ------------------------------------------
struct alignas(16) CPack {
    u64   w1y[512];   // [64][8] u64 = [64][16] floats: W1 rows 0..15 transposed
    float w1d[64];    // W1 row 32 (dose weights)
    float b2[16];
    float wr[16];
    float br;
    float t[64];
    float pad[3];
};
__device__   CPack g_p;   // staging (written by prep kernel)
__constant__ CPack c_p;   // read by main kernel

// Shared memory layout (float offsets)
#define S_W2  0                       // [64][16]  W2 row-major
#define S_C   1024                    // [64][BLOCK] per-thread const preactivation
#define S_TOTAL (S_C + MID * BLOCK)   // 15360 floats = 61440 bytes

// ---- packed f32x2 primitives ----------------------------------------------
__device__ __forceinline__ u64 pk2(float lo, float hi) {
    u64 r; asm("mov.b64 %0,{%1,%2};" : "=l"(r) : "f"(lo), "f"(hi)); return r;
}
__device__ __forceinline__ u64 pks(float x) { return pk2(x, x); }
__device__ __forceinline__ void upk(u64 v, float& lo, float& hi) {
    asm("mov.b64 {%0,%1},%2;" : "=f"(lo), "=f"(hi) : "l"(v));
}
__device__ __forceinline__ u64 f2fma(u64 a, u64 b, u64 c) {
    u64 d; asm("fma.rn.f32x2 %0,%1,%2,%3;" : "=l"(d) : "l"(a), "l"(b), "l"(c)); return d;
}
__device__ __forceinline__ u64 f2mul(u64 a, u64 b) {
    u64 d; asm("mul.rn.f32x2 %0,%1,%2;" : "=l"(d) : "l"(a), "l"(b)); return d;
}
__device__ __forceinline__ u64 f2add(u64 a, u64 b) {
    u64 d; asm("add.rn.f32x2 %0,%1,%2;" : "=l"(d) : "l"(a), "l"(b)); return d;
}
__device__ __forceinline__ float tanhap(float x) {
    float r; asm("tanh.approx.f32 %0,%1;" : "=f"(r) : "f"(x)); return r;
}

// ---- prep kernel: pack weights into g_p -----------------------------------
__global__ void prep_pack(const float* __restrict__ W1,
                          const float* __restrict__ b2,
                          const float* __restrict__ Wr,
                          const float* __restrict__ br,
                          const float* __restrict__ t_g)
{
    float* fp = (float*)&g_p;
    int tid = threadIdx.x;
    for (int idx = tid; idx < MID * 16; idx += blockDim.x) {
        int j = idx >> 4, i = idx & 15;
        fp[idx] = W1[i * MID + j];            // w1y transposed
    }
    for (int i = tid; i < 64; i += blockDim.x) {
        fp[1024 + i] = W1[32 * MID + i];      // w1d
        fp[1121 + i] = t_g[i];                // t
    }
    if (tid < 16) {
        fp[1088 + tid] = b2[tid];
        fp[1104 + tid] = Wr[tid];
    }
    if (tid == 0) fp[1120] = br[0];
}

// ---- ODE right-hand side: one MLP eval ------------------------------------
__device__ __forceinline__ void f_eval(
    float tv,
    const u64* __restrict__ y,        // [8] packed (16 floats)
    u64* __restrict__ kout,           // [8] packed
    const float* __restrict__ sm,
    int tid,
    const float* __restrict__ itm,    // [8] regs
    const float* __restrict__ idn)    // [8] regs
{
    float dose = 0.0f;
    #pragma unroll
    for (int n = 0; n < N_INJ; n++) {
        float d = tv - itm[n];
        dose += idn[n] * __expf(-0.5f * d * d);
    }
    dose = fminf(fmaxf(dose, 0.0f), 100.0f);

    const ulonglong2* __restrict__ w1y = (const ulonglong2*)c_p.w1y;   // CONST
    const ulonglong2* __restrict__ w2  = (const ulonglong2*)(sm + S_W2);
    const float* __restrict__ cg  = sm + S_C + tid;

    {   // kout = b2 (from constant)
        const ulonglong2* b2p = (const ulonglong2*)c_p.b2;
        ulonglong2 q0 = b2p[0], q1 = b2p[1], q2 = b2p[2], q3 = b2p[3];
        kout[0] = q0.x; kout[1] = q0.y; kout[2] = q1.x; kout[3] = q1.y;
        kout[4] = q2.x; kout[5] = q2.y; kout[6] = q3.x; kout[7] = q3.y;
    }

    #pragma unroll 4
    for (int j = 0; j < MID; j++) {
        float z0 = fmaf(dose, c_p.w1d[j], cg[j * BLOCK]);
        ulonglong2 a0 = w1y[j * 4 + 0], a1 = w1y[j * 4 + 1];
        ulonglong2 a2 = w1y[j * 4 + 2], a3 = w1y[j * 4 + 3];
        // two packed accumulator chains (16 MACs in 8 FFMA2)
        u64 s0 = f2fma(y[0], a0.x, pk2(z0, 0.0f));
        u64 s1 = f2mul(y[1], a0.y);
        s0 = f2fma(y[2], a1.x, s0);
        s1 = f2fma(y[3], a1.y, s1);
        s0 = f2fma(y[4], a2.x, s0);
        s1 = f2fma(y[5], a2.y, s1);
        s0 = f2fma(y[6], a3.x, s0);
        s1 = f2fma(y[7], a3.y, s1);
        u64 s = f2add(s0, s1);
        float slo, shi; upk(s, slo, shi);
        float a = tanhap(slo + shi);
        u64 aa = pks(a);

        ulonglong2 v0 = w2[j * 4 + 0], v1 = w2[j * 4 + 1];
        ulonglong2 v2 = w2[j * 4 + 2], v3 = w2[j * 4 + 3];
        kout[0] = f2fma(aa, v0.x, kout[0]);
        kout[1] = f2fma(aa, v0.y, kout[1]);
        kout[2] = f2fma(aa, v1.x, kout[2]);
        kout[3] = f2fma(aa, v1.y, kout[3]);
        kout[4] = f2fma(aa, v2.x, kout[4]);
        kout[5] = f2fma(aa, v2.y, kout[5]);
        kout[6] = f2fma(aa, v3.x, kout[6]);
        kout[7] = f2fma(aa, v3.y, kout[7]);
    }
}

extern "C" __global__ void __launch_bounds__(BLOCK, 1)
neural_ode_66236985639756(
    const float* __restrict__ sf_g,
    const float* __restrict__ it_g,
    const float* __restrict__ id_g,
    const float* __restrict__ W_se, const float* __restrict__ b_se,
    const float* __restrict__ W_i,  const float* __restrict__ b_i,
    const float* __restrict__ W1,   const float* __restrict__ b1,
    const float* __restrict__ W2,
    float* __restrict__ out)
{
    extern __shared__ float sm[];
    const int tid = threadIdx.x;
    const int b   = blockIdx.x * BLOCK + tid;
    const bool valid = (b < B_TOTAL);

    // ---- cooperative SMEM init (W2 only; rest is in constant) -------------
    for (int idx = tid; idx < MID * 16; idx += BLOCK) {
        sm[S_W2 + idx] = W2[idx];
    }

    // ---- per-thread static embed + h0 ------------------------------------
    float se[SHD];
    {
        float sfv[SID];
        #pragma unroll
        for (int i = 0; i < SID; i++) sfv[i] = valid ? sf_g[b * SID + i] : 0.0f;
        #pragma unroll
        for (int o = 0; o < SHD; o++) {
            float acc = b_se[o];
            #pragma unroll
            for (int i = 0; i < SID; i++) acc += sfv[i] * W_se[i * SHD + o];
            se[o] = fmaxf(acc, 0.0f);
        }
    }
    float h_s[OHD];
    #pragma unroll
    for (int o = 0; o < OHD; o++) {
        float acc = b_i[o];
        #pragma unroll
        for (int i = 0; i < SHD; i++) acc += se[i] * W_i[i * OHD + o];
        h_s[o] = acc;
    }
    // per-thread constant layer-1 preactivation: b1 + se @ W1[16:32]
    for (int j = 0; j < MID; j++) {
        float acc = b1[j];
        #pragma unroll
        for (int i = 0; i < SHD; i++) acc += se[i] * W1[(16 + i) * MID + j];
        sm[S_C + j * BLOCK + tid] = acc;
    }
    float itm[N_INJ], idn[N_INJ];
    #pragma unroll
    for (int n = 0; n < N_INJ; n++) {
        itm[n] = valid ? it_g[b * N_INJ + n] : 1.0e9f;
        idn[n] = valid ? id_g[b * N_INJ + n] : 0.0f;
    }
    __syncthreads();

    // packed state
    u64 h[8];
    #pragma unroll
    for (int p = 0; p < 8; p++) h[p] = pk2(h_s[2 * p], h_s[2 * p + 1]);

    const ulonglong2* __restrict__ wrp = (const ulonglong2*)c_p.wr;

    // ---- t=0 readout ------------------------------------------------------
    if (valid) {
        ulonglong2 wr0 = wrp[0], wr1 = wrp[1], wr2 = wrp[2], wr3 = wrp[3];
        u64 acc = f2mul(h[0], wr0.x);
        acc = f2fma(h[1], wr0.y, acc);
        acc = f2fma(h[2], wr1.x, acc);
        acc = f2fma(h[3], wr1.y, acc);
        acc = f2fma(h[4], wr2.x, acc);
        acc = f2fma(h[5], wr2.y, acc);
        acc = f2fma(h[6], wr3.x, acc);
        acc = f2fma(h[7], wr3.y, acc);
        float lo, hi; upk(acc, lo, hi);
        out[b * T_STEPS] = fmaxf(c_p.br + lo + hi, 0.0f);
    }

    // ---- dopri5 coefficients ---------------------------------------------
    const float A21 = 0.2f;
    const float A31 = 0.075f, A32 = 0.225f;
    const float A41 = (float)(44.0/45.0),      A42 = (float)(-56.0/15.0),
                A43 = (float)(32.0/9.0);
    const float A51 = (float)(19372.0/6561.0), A52 = (float)(-25360.0/2187.0),
                A53 = (float)(64448.0/6561.0), A54 = (float)(-212.0/729.0);
    const float A61 = (float)(9017.0/3168.0),  A62 = (float)(-355.0/33.0),
                A63 = (float)(46732.0/5247.0), A64 = (float)(49.0/176.0),
                A65 = (float)(-5103.0/18656.0);
    const float B1c = (float)(35.0/384.0),  B3c = (float)(500.0/1113.0),
                B4c = (float)(125.0/192.0), B5c = (float)(-2187.0/6784.0),
                B6c = (float)(11.0/84.0);
    const float C2 = 0.2f, C3 = 0.3f, C4 = 0.8f, C5 = (float)(8.0/9.0);

    u64 k1[8], k2[8], k3[8], k4[8], k5[8], y[8];

    #pragma unroll 1
    for (int step = 0; step < T_STEPS - 1; ++step) {
        float t0 = c_p.t[step], t1 = c_p.t[step + 1];
        float dt = (t1 - t0) * 0.5f;
        #pragma unroll 1
        for (int sub = 0; sub < 2; ++sub) {
            float tv = t0 + sub * dt;

            f_eval(tv, h, k1, sm, tid, itm, idn);

            {
                u64 c21 = pks(dt * A21);
                #pragma unroll
                for (int p = 0; p < 8; p++) y[p] = f2fma(c21, k1[p], h[p]);
            }
            f_eval(tv + C2 * dt, y, k2, sm, tid, itm, idn);

            {
                u64 c1 = pks(dt * A31), c2 = pks(dt * A32);
                #pragma unroll
                for (int p = 0; p < 8; p++)
                    y[p] = f2fma(c1, k1[p], f2fma(c2, k2[p], h[p]));
            }
            f_eval(tv + C3 * dt, y, k3, sm, tid, itm, idn);

            {
                u64 c1 = pks(dt * A41), c2 = pks(dt * A42), c3 = pks(dt * A43);
                #pragma unroll
                for (int p = 0; p < 8; p++) {
                    u64 acc = f2fma(c3, k3[p], h[p]);
                    acc = f2fma(c2, k2[p], acc);
                    y[p] = f2fma(c1, k1[p], acc);
                }
            }
            f_eval(tv + C4 * dt, y, k4, sm, tid, itm, idn);

            {
                u64 c1 = pks(dt * A51), c2 = pks(dt * A52),
                    c3 = pks(dt * A53), c4 = pks(dt * A54);
                #pragma unroll
                for (int p = 0; p < 8; p++) {
                    u64 acc = f2fma(c4, k4[p], h[p]);
                    acc = f2fma(c3, k3[p], acc);
                    acc = f2fma(c2, k2[p], acc);
                    y[p] = f2fma(c1, k1[p], acc);
                }
            }
            f_eval(tv + C5 * dt, y, k5, sm, tid, itm, idn);

            {
                u64 c1 = pks(dt * A61), c2 = pks(dt * A62), c3 = pks(dt * A63),
                    c4 = pks(dt * A64), c5 = pks(dt * A65);
                #pragma unroll
                for (int p = 0; p < 8; p++) {
                    u64 acc = f2fma(c5, k5[p], h[p]);
                    acc = f2fma(c4, k4[p], acc);
                    acc = f2fma(c3, k3[p], acc);
                    acc = f2fma(c2, k2[p], acc);
                    y[p] = f2fma(c1, k1[p], acc);
                }
            }
            // k2 is dead; reuse as k6
            f_eval(tv + dt, y, k2, sm, tid, itm, idn);

            {
                u64 c1 = pks(dt * B1c), c3 = pks(dt * B3c), c4 = pks(dt * B4c),
                    c5 = pks(dt * B5c), c6 = pks(dt * B6c);
                #pragma unroll
                for (int p = 0; p < 8; p++) {
                    u64 acc = f2fma(c6, k2[p], h[p]);
                    acc = f2fma(c5, k5[p], acc);
                    acc = f2fma(c4, k4[p], acc);
                    acc = f2fma(c3, k3[p], acc);
                    h[p] = f2fma(c1, k1[p], acc);
                }
            }
        }
        if (valid) {
            ulonglong2 wr0 = wrp[0], wr1 = wrp[1], wr2 = wrp[2], wr3 = wrp[3];
            u64 acc = f2mul(h[0], wr0.x);
            acc = f2fma(h[1], wr0.y, acc);
            acc = f2fma(h[2], wr1.x, acc);
            acc = f2fma(h[3], wr1.y, acc);
            acc = f2fma(h[4], wr2.x, acc);
            acc = f2fma(h[5], wr2.y, acc);
            acc = f2fma(h[6], wr3.x, acc);
            acc = f2fma(h[7], wr3.y, acc);
            float lo, hi; upk(acc, lo, hi);
            out[b * T_STEPS + step + 1] = fmaxf(c_p.br + lo + hi, 0.0f);
        }
    }
}

extern "C" void kernel_launch(void* const* d_in, const int* in_sizes, int n_in,
                              void* d_out, int out_size)
{
    (void)in_sizes; (void)n_in; (void)out_size;

    // 1) pack weights into staging buffer
    prep_pack<<<1, 256>>>((const float*)d_in[8],   // W1
                          (const float*)d_in[11],  // b2
                          (const float*)d_in[12],  // Wr
                          (const float*)d_in[13],  // br
                          (const float*)d_in[0]);  // t

    // 2) D2D copy staging -> constant memory (graph-capturable memcpy node)
    void* gaddr = nullptr;
    cudaGetSymbolAddress(&gaddr, g_p);
    cudaMemcpyToSymbolAsync(c_p, gaddr, sizeof(CPack), 0,
                            cudaMemcpyDeviceToDevice, 0);

    // 3) main kernel
    cudaFuncSetAttribute(neural_ode_66236985639756,
                         cudaFuncAttributeMaxDynamicSharedMemorySize,
                         S_TOTAL * sizeof(float));
    neural_ode_66236985639756<<<GRID, BLOCK, S_TOTAL * sizeof(float)>>>(
        (const float*)d_in[1],  // static_features
        (const float*)d_in[2],  // injection_times
        (const float*)d_in[3],  // injection_doses
        (const float*)d_in[4],  // W_se
        (const float*)d_in[5],  // b_se
        (const float*)d_in[6],  // W_i
        (const float*)d_in[7],  // b_i
        (const float*)d_in[8],  // W1
        (const float*)d_in[9],  // b1
        (const float*)d_in[10], // W2
        (float*)d_out);
}

// round 6
// speedup vs baseline: 1.0006x; 1.0006x over previous
#include <cuda_runtime.h>

// ---------------------------------------------------------------------------
// NeuralODEModel: persistent per-thread dopri5 (R3 shape: 224thr x 147 CTAs,
// 7 warps/SM) with layer-1 weights moved to __constant__ memory so the
// warp-uniform weight loads ride the constant/uniform port (LDCU) instead of
// the saturated L1/LSU path. W2 + per-thread cg stay in SMEM.
// Prep kernel packs weights into a __device__ staging buffer; a D2D
// cudaMemcpyToSymbolAsync copies it into constant memory (graph-capturable).
// ---------------------------------------------------------------------------

#define B_TOTAL 32768
#define T_STEPS 64
#define N_INJ   8
#define SID     7
#define SHD     16
#define OHD     16
#define MID     64
#define BLOCK   224
#define GRID    147   // 147*224 = 32928 >= 32768

typedef unsigned long long u64;

// ---- constant-memory weight pack ------------------------------------------
struct alignas(16) CPack {
    u64   w1y[512];   // [64][8] u64 = [64][16] floats: W1 rows 0..15 transposed
    float w1d[64];    // W1 row 32 (dose weights)
    float b2[16];
    float wr[16];
    float br;
    float t[64];
    float pad[3];
};
__device__   CPack g_p;   // staging (written by prep kernel)
__constant__ CPack c_p;   // read by main kernel

// Shared memory layout (float offsets)
#define S_W2  0                       // [64][16]  W2 row-major
#define S_C   1024                    // [64][BLOCK] per-thread const preactivation
#define S_TOTAL (S_C + MID * BLOCK)   // 15360 floats = 61440 bytes

// ---- packed f32x2 primitives ----------------------------------------------
__device__ __forceinline__ u64 pk2(float lo, float hi) {
    u64 r; asm("mov.b64 %0,{%1,%2};" : "=l"(r) : "f"(lo), "f"(hi)); return r;
}
__device__ __forceinline__ u64 pks(float x) { return pk2(x, x); }
__device__ __forceinline__ void upk(u64 v, float& lo, float& hi) {
    asm("mov.b64 {%0,%1},%2;" : "=f"(lo), "=f"(hi) : "l"(v));
}
__device__ __forceinline__ u64 f2fma(u64 a, u64 b, u64 c) {
    u64 d; asm("fma.rn.f32x2 %0,%1,%2,%3;" : "=l"(d) : "l"(a), "l"(b), "l"(c)); return d;
}
__device__ __forceinline__ u64 f2mul(u64 a, u64 b) {
    u64 d; asm("mul.rn.f32x2 %0,%1,%2;" : "=l"(d) : "l"(a), "l"(b)); return d;
}
__device__ __forceinline__ u64 f2add(u64 a, u64 b) {
    u64 d; asm("add.rn.f32x2 %0,%1,%2;" : "=l"(d) : "l"(a), "l"(b)); return d;
}
__device__ __forceinline__ float tanhap(float x) {
    float r; asm("tanh.approx.f32 %0,%1;" : "=f"(r) : "f"(x)); return r;
}

// ---- prep kernel: pack weights into g_p -----------------------------------
__global__ void prep_pack(const float* __restrict__ W1,
                          const float* __restrict__ b2,
                          const float* __restrict__ Wr,
                          const float* __restrict__ br,
                          const float* __restrict__ t_g)
{
    float* fp = (float*)&g_p;
    int tid = threadIdx.x;
    for (int idx = tid; idx < MID * 16; idx += blockDim.x) {
        int j = idx >> 4, i = idx & 15;
        fp[idx] = W1[i * MID + j];            // w1y transposed
    }
    for (int i = tid; i < 64; i += blockDim.x) {
        fp[1024 + i] = W1[32 * MID + i];      // w1d
        fp[1121 + i] = t_g[i];                // t
    }
    if (tid < 16) {
        fp[1088 + tid] = b2[tid];
        fp[1104 + tid] = Wr[tid];
    }
    if (tid == 0) fp[1120] = br[0];
}

// ---- ODE right-hand side: one MLP eval ------------------------------------
__device__ __forceinline__ void f_eval(
    float tv,
    const u64* __restrict__ y,        // [8] packed (16 floats)
    u64* __restrict__ kout,           // [8] packed
    const float* __restrict__ sm,
    int tid,
    const float* __restrict__ itm,    // [8] regs
    const float* __restrict__ idn)    // [8] regs
{
    float dose = 0.0f;
    #pragma unroll
    for (int n = 0; n < N_INJ; n++) {
        float d = tv - itm[n];
        dose += idn[n] * __expf(-0.5f * d * d);
    }
    dose = fminf(fmaxf(dose, 0.0f), 100.0f);

    const ulonglong2* __restrict__ w1y = (const ulonglong2*)c_p.w1y;   // CONST
    const ulonglong2* __restrict__ w2  = (const ulonglong2*)(sm + S_W2);
    const float* __restrict__ cg  = sm + S_C + tid;

    {   // kout = b2 (from constant)
        const ulonglong2* b2p = (const ulonglong2*)c_p.b2;
        ulonglong2 q0 = b2p[0], q1 = b2p[1], q2 = b2p[2], q3 = b2p[3];
        kout[0] = q0.x; kout[1] = q0.y; kout[2] = q1.x; kout[3] = q1.y;
        kout[4] = q2.x; kout[5] = q2.y; kout[6] = q3.x; kout[7] = q3.y;
    }

    #pragma unroll 4
    for (int j = 0; j < MID; j++) {
        float z0 = fmaf(dose, c_p.w1d[j], cg[j * BLOCK]);
        ulonglong2 a0 = w1y[j * 4 + 0], a1 = w1y[j * 4 + 1];
        ulonglong2 a2 = w1y[j * 4 + 2], a3 = w1y[j * 4 + 3];
        // two packed accumulator chains (16 MACs in 8 FFMA2)
        u64 s0 = f2fma(y[0], a0.x, pk2(z0, 0.0f));
        u64 s1 = f2mul(y[1], a0.y);
        s0 = f2fma(y[2], a1.x, s0);
        s1 = f2fma(y[3], a1.y, s1);
        s0 = f2fma(y[4], a2.x, s0);
        s1 = f2fma(y[5], a2.y, s1);
        s0 = f2fma(y[6], a3.x, s0);
        s1 = f2fma(y[7], a3.y, s1);
        u64 s = f2add(s0, s1);
        float slo, shi; upk(s, slo, shi);
        float a = tanhap(slo + shi);
        u64 aa = pks(a);

        ulonglong2 v0 = w2[j * 4 + 0], v1 = w2[j * 4 + 1];
        ulonglong2 v2 = w2[j * 4 + 2], v3 = w2[j * 4 + 3];
        kout[0] = f2fma(aa, v0.x, kout[0]);
        kout[1] = f2fma(aa, v0.y, kout[1]);
        kout[2] = f2fma(aa, v1.x, kout[2]);
        kout[3] = f2fma(aa, v1.y, kout[3]);
        kout[4] = f2fma(aa, v2.x, kout[4]);
        kout[5] = f2fma(aa, v2.y, kout[5]);
        kout[6] = f2fma(aa, v3.x, kout[6]);
        kout[7] = f2fma(aa, v3.y, kout[7]);
    }
}

extern "C" __global__ void __launch_bounds__(BLOCK, 1)
neural_ode_66236985639756(
    const float* __restrict__ sf_g,
    const float* __restrict__ it_g,
    const float* __restrict__ id_g,
    const float* __restrict__ W_se, const float* __restrict__ b_se,
    const float* __restrict__ W_i,  const float* __restrict__ b_i,
    const float* __restrict__ W1,   const float* __restrict__ b1,
    const float* __restrict__ W2,
    float* __restrict__ out)
{
    extern __shared__ float sm[];
    const int tid = threadIdx.x;
    const int b   = blockIdx.x * BLOCK + tid;
    const bool valid = (b < B_TOTAL);

    // ---- cooperative SMEM init (W2 only; rest is in constant) -------------
    for (int idx = tid; idx < MID * 16; idx += BLOCK) {
        sm[S_W2 + idx] = W2[idx];
    }

    // ---- per-thread static embed + h0 ------------------------------------
    float se[SHD];
    {
        float sfv[SID];
        #pragma unroll
        for (int i = 0; i < SID; i++) sfv[i] = valid ? sf_g[b * SID + i] : 0.0f;
        #pragma unroll
        for (int o = 0; o < SHD; o++) {
            float acc = b_se[o];
            #pragma unroll
            for (int i = 0; i < SID; i++) acc += sfv[i] * W_se[i * SHD + o];
            se[o] = fmaxf(acc, 0.0f);
        }
    }
    float h_s[OHD];
    #pragma unroll
    for (int o = 0; o < OHD; o++) {
        float acc = b_i[o];
        #pragma unroll
        for (int i = 0; i < SHD; i++) acc += se[i] * W_i[i * OHD + o];
        h_s[o] = acc;
    }
    // per-thread constant layer-1 preactivation: b1 + se @ W1[16:32]
    for (int j = 0; j < MID; j++) {
        float acc = b1[j];
        #pragma unroll
        for (int i = 0; i < SHD; i++) acc += se[i] * W1[(16 + i) * MID + j];
        sm[S_C + j * BLOCK + tid] = acc;
    }
    float itm[N_INJ], idn[N_INJ];
    #pragma unroll
    for (int n = 0; n < N_INJ; n++) {
        itm[n] = valid ? it_g[b * N_INJ + n] : 1.0e9f;
        idn[n] = valid ? id_g[b * N_INJ + n] : 0.0f;
    }
    __syncthreads();

    // packed state
    u64 h[8];
    #pragma unroll
    for (int p = 0; p < 8; p++) h[p] = pk2(h_s[2 * p], h_s[2 * p + 1]);

    const ulonglong2* __restrict__ wrp = (const ulonglong2*)c_p.wr;

    // ---- t=0 readout ------------------------------------------------------
    if (valid) {
        ulonglong2 wr0 = wrp[0], wr1 = wrp[1], wr2 = wrp[2], wr3 = wrp[3];
        u64 acc = f2mul(h[0], wr0.x);
        acc = f2fma(h[1], wr0.y, acc);
        acc = f2fma(h[2], wr1.x, acc);
        acc = f2fma(h[3], wr1.y, acc);
        acc = f2fma(h[4], wr2.x, acc);
        acc = f2fma(h[5], wr2.y, acc);
        acc = f2fma(h[6], wr3.x, acc);
        acc = f2fma(h[7], wr3.y, acc);
        float lo, hi; upk(acc, lo, hi);
        out[b * T_STEPS] = fmaxf(c_p.br + lo + hi, 0.0f);
    }

    // ---- dopri5 coefficients ---------------------------------------------
    const float A21 = 0.2f;
    const float A31 = 0.075f, A32 = 0.225f;
    const float A41 = (float)(44.0/45.0),      A42 = (float)(-56.0/15.0),
                A43 = (float)(32.0/9.0);
    const float A51 = (float)(19372.0/6561.0), A52 = (float)(-25360.0/2187.0),
                A53 = (float)(64448.0/6561.0), A54 = (float)(-212.0/729.0);
    const float A61 = (float)(9017.0/3168.0),  A62 = (float)(-355.0/33.0),
                A63 = (float)(46732.0/5247.0), A64 = (float)(49.0/176.0),
                A65 = (float)(-5103.0/18656.0);
    const float B1c = (float)(35.0/384.0),  B3c = (float)(500.0/1113.0),
                B4c = (float)(125.0/192.0), B5c = (float)(-2187.0/6784.0),
                B6c = (float)(11.0/84.0);
    const float C2 = 0.2f, C3 = 0.3f, C4 = 0.8f, C5 = (float)(8.0/9.0);

    u64 k1[8], k2[8], k3[8], k4[8], k5[8], y[8];

    #pragma unroll 1
    for (int step = 0; step < T_STEPS - 1; ++step) {
        float t0 = c_p.t[step], t1 = c_p.t[step + 1];
        float dt = (t1 - t0) * 0.5f;
        #pragma unroll 1
        for (int sub = 0; sub < 2; ++sub) {
            float tv = t0 + sub * dt;

            f_eval(tv, h, k1, sm, tid, itm, idn);

            {
                u64 c21 = pks(dt * A21);
                #pragma unroll
                for (int p = 0; p < 8; p++) y[p] = f2fma(c21, k1[p], h[p]);
            }
            f_eval(tv + C2 * dt, y, k2, sm, tid, itm, idn);

            {
                u64 c1 = pks(dt * A31), c2 = pks(dt * A32);
                #pragma unroll
                for (int p = 0; p < 8; p++)
                    y[p] = f2fma(c1, k1[p], f2fma(c2, k2[p], h[p]));
            }
            f_eval(tv + C3 * dt, y, k3, sm, tid, itm, idn);

            {
                u64 c1 = pks(dt * A41), c2 = pks(dt * A42), c3 = pks(dt * A43);
                #pragma unroll
                for (int p = 0; p < 8; p++) {
                    u64 acc = f2fma(c3, k3[p], h[p]);
                    acc = f2fma(c2, k2[p], acc);
                    y[p] = f2fma(c1, k1[p], acc);
                }
            }
            f_eval(tv + C4 * dt, y, k4, sm, tid, itm, idn);

            {
                u64 c1 = pks(dt * A51), c2 = pks(dt * A52),
                    c3 = pks(dt * A53), c4 = pks(dt * A54);
                #pragma unroll
                for (int p = 0; p < 8; p++) {
                    u64 acc = f2fma(c4, k4[p], h[p]);
                    acc = f2fma(c3, k3[p], acc);
                    acc = f2fma(c2, k2[p], acc);
                    y[p] = f2fma(c1, k1[p], acc);
                }
            }
            f_eval(tv + C5 * dt, y, k5, sm, tid, itm, idn);

            {
                u64 c1 = pks(dt * A61), c2 = pks(dt * A62), c3 = pks(dt * A63),
                    c4 = pks(dt * A64), c5 = pks(dt * A65);
                #pragma unroll
                for (int p = 0; p < 8; p++) {
                    u64 acc = f2fma(c5, k5[p], h[p]);
                    acc = f2fma(c4, k4[p], acc);
                    acc = f2fma(c3, k3[p], acc);
                    acc = f2fma(c2, k2[p], acc);
                    y[p] = f2fma(c1, k1[p], acc);
                }
            }
            // k2 is dead; reuse as k6
            f_eval(tv + dt, y, k2, sm, tid, itm, idn);

            {
                u64 c1 = pks(dt * B1c), c3 = pks(dt * B3c), c4 = pks(dt * B4c),
                    c5 = pks(dt * B5c), c6 = pks(dt * B6c);
                #pragma unroll
                for (int p = 0; p < 8; p++) {
                    u64 acc = f2fma(c6, k2[p], h[p]);
                    acc = f2fma(c5, k5[p], acc);
                    acc = f2fma(c4, k4[p], acc);
                    acc = f2fma(c3, k3[p], acc);
                    h[p] = f2fma(c1, k1[p], acc);
                }
            }
        }
        if (valid) {
            ulonglong2 wr0 = wrp[0], wr1 = wrp[1], wr2 = wrp[2], wr3 = wrp[3];
            u64 acc = f2mul(h[0], wr0.x);
            acc = f2fma(h[1], wr0.y, acc);
            acc = f2fma(h[2], wr1.x, acc);
            acc = f2fma(h[3], wr1.y, acc);
            acc = f2fma(h[4], wr2.x, acc);
            acc = f2fma(h[5], wr2.y, acc);
            acc = f2fma(h[6], wr3.x, acc);
            acc = f2fma(h[7], wr3.y, acc);
            float lo, hi; upk(acc, lo, hi);
            out[b * T_STEPS + step + 1] = fmaxf(c_p.br + lo + hi, 0.0f);
        }
    }
}

extern "C" void kernel_launch(void* const* d_in, const int* in_sizes, int n_in,
                              void* d_out, int out_size)
{
    (void)in_sizes; (void)n_in; (void)out_size;

    // 1) pack weights into staging buffer
    prep_pack<<<1, 256>>>((const float*)d_in[8],   // W1
                          (const float*)d_in[11],  // b2
                          (const float*)d_in[12],  // Wr
                          (const float*)d_in[13],  // br
                          (const float*)d_in[0]);  // t

    // 2) D2D copy staging -> constant memory (graph-capturable memcpy node)
    void* gaddr = nullptr;
    cudaGetSymbolAddress(&gaddr, g_p);
    cudaMemcpyToSymbolAsync(c_p, gaddr, sizeof(CPack), 0,
                            cudaMemcpyDeviceToDevice, 0);

    // 3) main kernel
    cudaFuncSetAttribute(neural_ode_66236985639756,
                         cudaFuncAttributeMaxDynamicSharedMemorySize,
                         S_TOTAL * sizeof(float));
    neural_ode_66236985639756<<<GRID, BLOCK, S_TOTAL * sizeof(float)>>>(
        (const float*)d_in[1],  // static_features
        (const float*)d_in[2],  // injection_times
        (const float*)d_in[3],  // injection_doses
        (const float*)d_in[4],  // W_se
        (const float*)d_in[5],  // b_se
        (const float*)d_in[6],  // W_i
        (const float*)d_in[7],  // b_i
        (const float*)d_in[8],  // W1
        (const float*)d_in[9],  // b1
        (const float*)d_in[10], // W2
        (float*)d_out);
}

// round 9
// speedup vs baseline: 3.9351x; 3.9328x over previous
#include <cuda_runtime.h>

#define T_STEPS 64
#define N_INJ 8
#define SID 7
#define BLOCK 256
#define GRID 128

#define SM_T  0
#define SM_SE 1024
#define SM_CG (SM_SE + 16384)
#define SM_TOTAL (SM_CG + 65536)

typedef unsigned u32;

__device__ __forceinline__ void bf16split2(float x0, float x1, u32& h, u32& l) {
    asm("cvt.rn.bf16x2.f32 %0, %1, %2;" : "=r"(h) : "f"(x1), "f"(x0));
    float h0 = __uint_as_float(h << 16);
    float h1 = __uint_as_float(h & 0xffff0000u);
    asm("cvt.rn.bf16x2.f32 %0, %1, %2;" : "=r"(l) : "f"(x1 - h1), "f"(x0 - h0));
}
__device__ __forceinline__ float tanhap(float x) {
    float r; asm("tanh.approx.f32 %0,%1;" : "=f"(r) : "f"(x)); return r;
}
__device__ __forceinline__ void mma4(float& c0, float& c1, float& c2, float& c3,
                                     const u32* a, u32 b0, u32 b1) {
    asm volatile("mma.sync.aligned.m16n8k16.row.col.f32.bf16.bf16.f32 "
        "{%0,%1,%2,%3},{%4,%5,%6,%7},{%8,%9},{%0,%1,%2,%3};"
        : "+f"(c0), "+f"(c1), "+f"(c2), "+f"(c3)
        : "r"(a[0]), "r"(a[1]), "r"(a[2]), "r"(a[3]), "r"(b0), "r"(b1));
}

// one MLP eval: ys[16] (C-frag state) -> ko[16]
__device__ __forceinline__ void feval(
    float tv, const float* __restrict__ ys, float* __restrict__ ko,
    const u32* __restrict__ b1h, const u32* __restrict__ b1l,
    const u32* __restrict__ b2h, const u32* __restrict__ b2l,
    const float* __restrict__ w1dA, const float* __restrict__ w1dB,
    const float* __restrict__ b2q, const char* __restrict__ cgT,
    const float* __restrict__ itm, const float* __restrict__ idn, int g)
{
    float dose = 0.f;
    #pragma unroll
    for (int n = 0; n < N_INJ; n++) {
        float d = tv - itm[n];
        dose += idn[n] * __expf(-0.5f * d * d);
    }
    dose = fminf(fmaxf(dose, 0.f), 100.f);

    #pragma unroll
    for (int mt = 0; mt < 2; mt++) {
        float d0 = __shfl_sync(0xffffffffu, dose, 16 * mt + g);
        float d1 = __shfl_sync(0xffffffffu, dose, 16 * mt + g + 8);
        const float* y = ys + mt * 8;
        u32 a1h[4], a1l[4];
        bf16split2(y[0], y[1], a1h[0], a1l[0]);
        bf16split2(y[2], y[3], a1h[1], a1l[1]);
        bf16split2(y[4], y[5], a1h[2], a1l[2]);
        bf16split2(y[6], y[7], a1h[3], a1l[3]);

        u32 a2h[16], a2l[16];
        #pragma unroll
        for (int nt = 0; nt < 8; nt++) {
            float4 cg = *(const float4*)(cgT + (mt * 8 + nt) * 512);
            float z0 = fmaf(d0, w1dA[nt], cg.x);
            float z1 = fmaf(d0, w1dB[nt], cg.y);
            float z2 = fmaf(d1, w1dA[nt], cg.z);
            float z3 = fmaf(d1, w1dB[nt], cg.w);
            mma4(z0, z1, z2, z3, a1h, b1h[nt * 2], b1h[nt * 2 + 1]);
            mma4(z0, z1, z2, z3, a1h, b1l[nt * 2], b1l[nt * 2 + 1]);
            mma4(z0, z1, z2, z3, a1l, b1h[nt * 2], b1h[nt * 2 + 1]);
            float t0 = tanhap(z0), t1 = tanhap(z1);
            float t2 = tanhap(z2), t3 = tanhap(z3);
            int base = (nt >> 1) * 4 + (nt & 1) * 2;
            bf16split2(t0, t1, a2h[base], a2l[base]);
            bf16split2(t2, t3, a2h[base + 1], a2l[base + 1]);
        }
        #pragma unroll
        for (int nt2 = 0; nt2 < 2; nt2++) {
            float c0 = b2q[nt2 * 2], c1 = b2q[nt2 * 2 + 1];
            float c2 = c0, c3 = c1;
            #pragma unroll
            for (int kt = 0; kt < 4; kt++) {
                const u32* bh = b2h + kt * 4 + nt2 * 2;
                const u32* bl = b2l + kt * 4 + nt2 * 2;
                mma4(c0, c1, c2, c3, a2h + kt * 4, bh[0], bh[1]);
                mma4(c0, c1, c2, c3, a2h + kt * 4, bl[0], bl[1]);
                mma4(c0, c1, c2, c3, a2l + kt * 4, bh[0], bh[1]);
            }
            ko[mt * 8 + nt2 * 4 + 0] = c0;
            ko[mt * 8 + nt2 * 4 + 1] = c1;
            ko[mt * 8 + nt2 * 4 + 2] = c2;
            ko[mt * 8 + nt2 * 4 + 3] = c3;
        }
    }
}

__device__ __forceinline__ void writeout(
    const float* __restrict__ h, const float* __restrict__ wrq, float brv,
    int rbase, int g, int c, int step, float* __restrict__ out)
{
    #pragma unroll
    for (int mt = 0; mt < 2; mt++)
    #pragma unroll
    for (int rh = 0; rh < 2; rh++) {
        float p = h[mt * 8 + rh * 2 + 0] * wrq[0] + h[mt * 8 + rh * 2 + 1] * wrq[1]
                + h[mt * 8 + 4 + rh * 2 + 0] * wrq[2] + h[mt * 8 + 4 + rh * 2 + 1] * wrq[3];
        p += __shfl_xor_sync(0xffffffffu, p, 1);
        p += __shfl_xor_sync(0xffffffffu, p, 2);
        if (c == 0)
            out[(rbase + 16 * mt + g + 8 * rh) * T_STEPS + step] = fmaxf(brv + p, 0.f);
    }
}

extern "C" __global__ void __launch_bounds__(BLOCK, 1)
neural_ode_66236985639756(
    const float* __restrict__ t_g,  const float* __restrict__ sf_g,
    const float* __restrict__ it_g, const float* __restrict__ id_g,
    const float* __restrict__ W_se, const float* __restrict__ b_se,
    const float* __restrict__ W_i,  const float* __restrict__ b_i,
    const float* __restrict__ W1,   const float* __restrict__ b1,
    const float* __restrict__ W2,   const float* __restrict__ b2,
    const float* __restrict__ Wr,   const float* __restrict__ br,
    float* __restrict__ out)
{
    extern __shared__ __align__(16) char smem[];
    float* smT = (float*)(smem + SM_T);
    float* seA = (float*)(smem + SM_SE);
    const int tid = threadIdx.x;
    const int wid = tid >> 5;
    const int lane = tid & 31;
    const int g = lane >> 2;
    const int c = lane & 3;
    const int rbase = blockIdx.x * BLOCK + wid * 32;   // warp's first row
    const int ro = rbase + lane;                        // this thread's own row

    for (int i = tid; i < T_STEPS; i += BLOCK) smT[i] = t_g[i];

    // own-row static embed -> smem
    {
        float sfv[SID];
        #pragma unroll
        for (int i = 0; i < SID; i++) sfv[i] = sf_g[ro * SID + i];
        #pragma unroll
        for (int o = 0; o < 16; o++) {
            float acc = b_se[o];
            #pragma unroll
            for (int i = 0; i < SID; i++) acc += sfv[i] * W_se[i * 16 + o];
            seA[(wid * 32 + lane) * 16 + o] = fmaxf(acc, 0.f);
        }
    }
    __syncthreads();

    // h0 in C-frag state layout
    float h[16];
    #pragma unroll
    for (int mt = 0; mt < 2; mt++)
    #pragma unroll
    for (int e = 0; e < 8; e++) {
        int col = 2 * c + (e & 1) + ((e >> 2) & 1) * 8;
        int rl = wid * 32 + 16 * mt + g + ((e >> 1) & 1) * 8;
        float acc = b_i[col];
        #pragma unroll
        for (int i = 0; i < 16; i++) acc += seA[rl * 16 + i] * W_i[i * 16 + col];
        h[mt * 8 + e] = acc;
    }
    // cg (b1 + se@W1[16:32]) into C-frag-ordered smem
    const char* cgT = smem + SM_CG + wid * 8192 + lane * 16;
    for (int mt = 0; mt < 2; mt++)
    for (int nt = 0; nt < 8; nt++) {
        float v[4];
        #pragma unroll
        for (int q = 0; q < 4; q++) {
            int j = 8 * nt + 2 * c + (q & 1);
            int rl = wid * 32 + 16 * mt + g + (q >> 1) * 8;
            float acc = b1[j];
            #pragma unroll
            for (int i = 0; i < 16; i++) acc += seA[rl * 16 + i] * W1[(16 + i) * 64 + j];
            v[q] = acc;
        }
        *(float4*)(smem + SM_CG + (wid * 16 + mt * 8 + nt) * 512 + lane * 16)
            = make_float4(v[0], v[1], v[2], v[3]);
    }

    // register-resident B fragments
    u32 b1h[16], b1l[16];
    float w1dA[8], w1dB[8];
    #pragma unroll
    for (int nt = 0; nt < 8; nt++) {
        bf16split2(W1[(2 * c) * 64 + 8 * nt + g], W1[(2 * c + 1) * 64 + 8 * nt + g],
                   b1h[nt * 2], b1l[nt * 2]);
        bf16split2(W1[(2 * c + 8) * 64 + 8 * nt + g], W1[(2 * c + 9) * 64 + 8 * nt + g],
                   b1h[nt * 2 + 1], b1l[nt * 2 + 1]);
        w1dA[nt] = W1[32 * 64 + 8 * nt + 2 * c];
        w1dB[nt] = W1[32 * 64 + 8 * nt + 2 * c + 1];
    }
    u32 b2h[16], b2l[16];
    #pragma unroll
    for (int kt = 0; kt < 4; kt++)
    #pragma unroll
    for (int nt2 = 0; nt2 < 2; nt2++) {
        int o = 8 * nt2 + g;
        bf16split2(W2[(16 * kt + 2 * c) * 16 + o], W2[(16 * kt + 2 * c + 1) * 16 + o],
                   b2h[kt * 4 + nt2 * 2], b2l[kt * 4 + nt2 * 2]);
        bf16split2(W2[(16 * kt + 2 * c + 8) * 16 + o], W2[(16 * kt + 2 * c + 9) * 16 + o],
                   b2h[kt * 4 + nt2 * 2 + 1], b2l[kt * 4 + nt2 * 2 + 1]);
    }
    float b2q[4] = { b2[2 * c], b2[2 * c + 1], b2[2 * c + 8], b2[2 * c + 9] };
    float wrq[4] = { Wr[2 * c], Wr[2 * c + 1], Wr[2 * c + 8], Wr[2 * c + 9] };
    const float brv = br[0];

    float itm[N_INJ], idn[N_INJ];
    #pragma unroll
    for (int n = 0; n < N_INJ; n++) {
        itm[n] = it_g[ro * N_INJ + n];
        idn[n] = id_g[ro * N_INJ + n];
    }
    __syncthreads();

    writeout(h, wrq, brv, rbase, g, c, 0, out);

    const float A21 = 0.2f, A31 = 0.075f, A32 = 0.225f;
    const float A41 = (float)(44.0/45.0), A42 = (float)(-56.0/15.0), A43 = (float)(32.0/9.0);
    const float A51 = (float)(19372.0/6561.0), A52 = (float)(-25360.0/2187.0),
                A53 = (float)(64448.0/6561.0), A54 = (float)(-212.0/729.0);
    const float A61 = (float)(9017.0/3168.0), A62 = (float)(-355.0/33.0),
                A63 = (float)(46732.0/5247.0), A64 = (float)(49.0/176.0),
                A65 = (float)(-5103.0/18656.0);
    const float B1c = (float)(35.0/384.0), B3c = (float)(500.0/1113.0),
                B4c = (float)(125.0/192.0), B5c = (float)(-2187.0/6784.0),
                B6c = (float)(11.0/84.0);
    const float C2 = 0.2f, C3 = 0.3f, C4 = 0.8f, C5 = (float)(8.0/9.0);

    float k1[16], k2[16], k3[16], k4[16], k5[16], y[16];

    #pragma unroll 1
    for (int step = 0; step < T_STEPS - 1; ++step) {
        float t0 = smT[step], t1 = smT[step + 1];
        float dt = (t1 - t0) * 0.5f;
        #pragma unroll 1
        for (int sub = 0; sub < 2; ++sub) {
            float tv = t0 + sub * dt;
            feval(tv, h, k1, b1h, b1l, b2h, b2l, w1dA, w1dB, b2q, cgT, itm, idn, g);
            #pragma unroll
            for (int i = 0; i < 16; i++) y[i] = fmaf(dt * A21, k1[i], h[i]);
            feval(tv + C2 * dt, y, k2, b1h, b1l, b2h, b2l, w1dA, w1dB, b2q, cgT, itm, idn, g);
            #pragma unroll
            for (int i = 0; i < 16; i++)
                y[i] = fmaf(dt * A31, k1[i], fmaf(dt * A32, k2[i], h[i]));
            feval(tv + C3 * dt, y, k3, b1h, b1l, b2h, b2l, w1dA, w1dB, b2q, cgT, itm, idn, g);
            #pragma unroll
            for (int i = 0; i < 16; i++) {
                float a = fmaf(dt * A43, k3[i], h[i]);
                a = fmaf(dt * A42, k2[i], a);
                y[i] = fmaf(dt * A41, k1[i], a);
            }
            feval(tv + C4 * dt, y, k4, b1h, b1l, b2h, b2l, w1dA, w1dB, b2q, cgT, itm, idn, g);
            #pragma unroll
            for (int i = 0; i < 16; i++) {
                float a = fmaf(dt * A54, k4[i], h[i]);
                a = fmaf(dt * A53, k3[i], a);
                a = fmaf(dt * A52, k2[i], a);
                y[i] = fmaf(dt * A51, k1[i], a);
            }
            feval(tv + C5 * dt, y, k5, b1h, b1l, b2h, b2l, w1dA, w1dB, b2q, cgT, itm, idn, g);
            #pragma unroll
            for (int i = 0; i < 16; i++) {
                float a = fmaf(dt * A65, k5[i], h[i]);
                a = fmaf(dt * A64, k4[i], a);
                a = fmaf(dt * A63, k3[i], a);
                a = fmaf(dt * A62, k2[i], a);
                y[i] = fmaf(dt * A61, k1[i], a);
            }
            feval(tv + dt, y, k2, b1h, b1l, b2h, b2l, w1dA, w1dB, b2q, cgT, itm, idn, g);
            #pragma unroll
            for (int i = 0; i < 16; i++) {
                float a = fmaf(dt * B6c, k2[i], h[i]);
                a = fmaf(dt * B5c, k5[i], a);
                a = fmaf(dt * B4c, k4[i], a);
                a = fmaf(dt * B3c, k3[i], a);
                h[i] = fmaf(dt * B1c, k1[i], a);
            }
        }
        writeout(h, wrq, brv, rbase, g, c, step + 1, out);
    }
}

extern "C" void kernel_launch(void* const* d_in, const int* in_sizes, int n_in,
                              void* d_out, int out_size)
{
    (void)in_sizes; (void)n_in; (void)out_size;
    cudaFuncSetAttribute(neural_ode_66236985639756,
                         cudaFuncAttributeMaxDynamicSharedMemorySize, SM_TOTAL);
    neural_ode_66236985639756<<<GRID, BLOCK, SM_TOTAL>>>(
        (const float*)d_in[0],  (const float*)d_in[1],
        (const float*)d_in[2],  (const float*)d_in[3],
        (const float*)d_in[4],  (const float*)d_in[5],
        (const float*)d_in[6],  (const float*)d_in[7],
        (const float*)d_in[8],  (const float*)d_in[9],
        (const float*)d_in[10], (const float*)d_in[11],
        (const float*)d_in[12], (const float*)d_in[13],
        (float*)d_out);
}